// round 15
// baseline (speedup 1.0000x reference)
#include <cuda_runtime.h>
#include <cuda_fp16.h>
#include <cstdint>

// FrameAlignedGNNLayer3D via mma.sync (sm_100-safe HMMA path).
// R15: WEIGHT-RESIDENT REGISTERS. R14 profile: L1TEX 54.7% top pipe, of which
// ~95% is loop-invariant weight ldmatrix (W1 8 + W2 32 ldm4 per 32-row chunk).
// Now each warp loads W1 (16 regs) + W2 (64 regs) B-fragments ONCE before the
// persistent loop; the loop has only 2 X-ldmatrix per chunk. ldmatrix->mma
// chains vanish; mma stream has 8 independent accumulator chains.
// 128-thr CTAs, launch_bounds(128,2): ~8 warps/SM, ~180 regs.
// Single-fp16, warp-autonomous chunks, tanh-silu retained.

#define S_SLOTS 4
#define NTHREADS 128
#define NWARPS 4
#define MAX_NODES (1 << 20)

// ---- smem layout (static, ~16KB) ----
#define XPITCH 48      // 16 fp16 (32B) + 16B pad -> conflict-free ldmatrix
#define WPITCH1 48
#define WPITCH2 144    // 64 fp16 (128B) + 16B pad
#define OFF_XHI  0                              // 128 rows x 48B (warp-private 32-row regions)
#define OFF_W1H  (OFF_XHI + 128 * XPITCH)       // 6144
#define OFF_W2H  (OFF_W1H + 64 * WPITCH1)       // 9216
#define OFF_B1   (OFF_W2H + 64 * WPITCH2)       // 18432
#define OFF_B2   (OFF_B1 + 256)
#define OFF_W3   (OFF_B2 + 256)                 // 64 float2 pairs
#define OFF_B3   (OFF_W3 + 512)
#define SMEM_BYTES (OFF_B3 + 16)

__device__ int g_edge_is_i64;
__device__ float4 g_node_rec[MAX_NODES];   // {x0, x1, x2, theta}

__global__ void init_kernel(float* __restrict__ out, int n,
                            const int* __restrict__ edge32, int n32,
                            const float* __restrict__ x,
                            const float* __restrict__ theta, int nN) {
    int idx = blockIdx.x * blockDim.x + threadIdx.x;
    if (idx < n) out[idx] = 0.0f;
    if (idx < nN) {
        g_node_rec[idx] = make_float4(x[3 * idx + 0], x[3 * idx + 1],
                                      x[3 * idx + 2], theta[idx]);
    }
    if (idx == 0) {
        int any_nonzero = 0;
        for (int s = 0; s < 16; s++) {
            long long pos = 1 + (long long)s * ((n32 - 2) / 16);
            pos |= 1;
            if (pos < n32) any_nonzero |= (edge32[pos] != 0);
        }
        g_edge_is_i64 = any_nonzero ? 0 : 1;
    }
}

// silu via hardware tanh: silu(v) = 0.5v * (1 + tanh(0.5v)). 1 MUFU + 2 FMA.
__device__ __forceinline__ float silu(float v) {
    float h = 0.5f * v;
    float t;
    asm("tanh.approx.f32 %0, %1;" : "=f"(t) : "f"(h));
    return fmaf(h, t, h);
}

__device__ __forceinline__ uint32_t smem_u32(const void* p) {
    uint32_t a;
    asm("{ .reg .u64 t; cvta.to.shared.u64 t, %1; cvt.u32.u64 %0, t; }" : "=r"(a) : "l"(p));
    return a;
}

__device__ __forceinline__ void ldm4(uint32_t addr, uint32_t& r0, uint32_t& r1,
                                     uint32_t& r2, uint32_t& r3) {
    asm volatile("ldmatrix.sync.aligned.m8n8.x4.shared.b16 {%0,%1,%2,%3}, [%4];"
                 : "=r"(r0), "=r"(r1), "=r"(r2), "=r"(r3) : "r"(addr));
}

__device__ __forceinline__ void mma16816(float* c, const uint32_t* a,
                                         uint32_t b0, uint32_t b1) {
    asm volatile(
        "mma.sync.aligned.m16n8k16.row.col.f32.f16.f16.f32 "
        "{%0,%1,%2,%3}, {%4,%5,%6,%7}, {%8,%9}, {%0,%1,%2,%3};"
        : "+f"(c[0]), "+f"(c[1]), "+f"(c[2]), "+f"(c[3])
        : "r"(a[0]), "r"(a[1]), "r"(a[2]), "r"(a[3]), "r"(b0), "r"(b1));
}

__device__ __forceinline__ uint32_t pack_hf2(float v0, float v1) {
    __half2 p = __floats2half2_rn(v0, v1);   // .x = v0 (low half)
    return *reinterpret_cast<uint32_t*>(&p);
}

__global__ __launch_bounds__(NTHREADS, 2)
void gnn_mma_kernel(
    const float* __restrict__ H, const int* __restrict__ edge,
    const float* __restrict__ W1, const float* __restrict__ b1,
    const float* __restrict__ W2, const float* __restrict__ b2,
    const float* __restrict__ W3, const float* __restrict__ b3,
    float* __restrict__ out, int nE, int nchunks)
{
    __shared__ __align__(16) char smem[SMEM_BYTES];
    const uint32_t sb = smem_u32(smem);

    const int t    = threadIdx.x;
    const int lane = t & 31;
    const int w    = t >> 5;           // warp id 0..3
    const int is64 = g_edge_is_i64;
    const long long items = (long long)nE * S_SLOTS;

    // ================= stage weights to smem ONCE (single fp16) ==============
    for (int idx = t; idx < 64 * 10; idx += NTHREADS) {
        int kk = idx / 64, n = idx % 64;
        *(__half*)(smem + OFF_W1H + n * WPITCH1 + kk * 2) = __float2half_rn(W1[kk * 64 + n]);
    }
    if (t < 64) {  // zero pad kk 10..15 of W1
        for (int kk = 10; kk < 16; kk++)
            *(__half*)(smem + OFF_W1H + t * WPITCH1 + kk * 2) = __float2half_rn(0.f);
    }
    for (int idx = t; idx < 64 * 64; idx += NTHREADS) {
        int k = idx >> 6, n = idx & 63;
        *(__half*)(smem + OFF_W2H + n * WPITCH2 + k * 2) = __float2half_rn(W2[k * 64 + n]);
    }
    if (t < 64) {
        ((float*)(smem + OFF_B1))[t] = b1[t];
        ((float*)(smem + OFF_B2))[t] = b2[t];
        ((float2*)(smem + OFF_W3))[t] = make_float2(W3[2 * t], W3[2 * t + 1]);
    }
    if (t < 2) ((float*)(smem + OFF_B3))[t] = b3[t];
    __syncthreads();   // ONLY block barrier.

    // ================= fragment address precompute =================
    const int sel = lane >> 3;
    const int r8  = lane & 7;
    const uint32_t a_off0 = (uint32_t)((w * 32 + r8 + (sel & 1) * 8) * XPITCH + (sel >> 1) * 16);
    const uint32_t w1_off = (uint32_t)(((sel >> 1) * 8 + r8) * WPITCH1 + (sel & 1) * 16);
    const uint32_t w2_off = (uint32_t)(((sel >> 1) * 8 + r8) * WPITCH2 + (sel & 1) * 16);
    const int cb = 2 * (lane & 3);

    // ================= load weight fragments into registers (ONCE) ===========
    uint32_t w1f[16];   // 8 n-tiles x (b0,b1), K=16
    #pragma unroll
    for (int jp = 0; jp < 8; jp += 2)
        ldm4(sb + OFF_W1H + jp * 8 * WPITCH1 + w1_off,
             w1f[2 * jp + 0], w1f[2 * jp + 1], w1f[2 * jp + 2], w1f[2 * jp + 3]);

    uint32_t w2f[64];   // [q][n-tile] -> 4 k-tiles x 8 n-tiles x (b0,b1)
    #pragma unroll
    for (int q = 0; q < 4; q++)
        #pragma unroll
        for (int jp = 0; jp < 8; jp += 2)
            ldm4(sb + OFF_W2H + jp * 8 * WPITCH2 + q * 32 + w2_off,
                 w2f[q * 16 + 2 * jp + 0], w2f[q * 16 + 2 * jp + 1],
                 w2f[q * 16 + 2 * jp + 2], w2f[q * 16 + 2 * jp + 3]);

    const int gw = blockIdx.x * NWARPS + w;     // global warp id
    const int TW = gridDim.x * NWARPS;          // total warps

    const float bb0 = ((float*)(smem + OFF_B3))[0];
    const float bb1 = ((float*)(smem + OFF_B3))[1];

    // ================= warp-autonomous chunk loop (32 rows/chunk) ============
    for (long long chunk = gw; chunk < nchunks; chunk += TW) {

        // ---- features: every lane computes one row into warp-private smem ----
        {
            const long long item = chunk * 32 + lane;
            float f[10] = {0, 0, 0, 0, 0, 0, 0, 0, 0, 0};
            if (item < items) {
                const int e = (int)(item >> 2);
                const int s = (int)(item & 3);
                int i_node, j_node;
                if (is64) {
                    const long long* e64 = (const long long*)edge;
                    i_node = (int)e64[e]; j_node = (int)e64[(long long)nE + e];
                } else {
                    i_node = edge[e]; j_node = edge[nE + e];
                }
                const float4 ri = g_node_rec[i_node];
                const float4 rj = g_node_rec[j_node];
                const float dx0 = rj.x - ri.x;
                const float dx1 = rj.y - ri.y;
                const float dx2 = rj.z - ri.z;
                const float rxy2 = dx0 * dx0 + dx1 * dx1;
                float s2, c2; sincosf(2.0f * (rj.w - ri.w), &s2, &c2);
                float sp, cp; sincosf(atan2f(dx1, dx0) - ri.w, &sp, &cp);
                const float sgn = (dx2 > 0.0f) ? 1.0f : ((dx2 < 0.0f) ? -1.0f : 0.0f);
                const float2 hv = *(const float2*)(H + ((long long)j_node * S_SLOTS + s) * 2);
                f[0] = c2 * hv.x - s2 * hv.y;
                f[1] = s2 * hv.x + c2 * hv.y;
                f[2] = sqrtf(rxy2 + dx2 * dx2);
                f[3] = sqrtf(rxy2);
                f[4] = dx2;
                f[5] = sp;  f[6] = cp;  f[7] = s2;  f[8] = c2;  f[9] = sgn * s2;
            }
            uint32_t ph[8];
            #pragma unroll
            for (int c = 0; c < 10; c += 2)
                ph[c >> 1] = pack_hf2(f[c], f[c + 1]);
            ph[5] = 0u; ph[6] = 0u; ph[7] = 0u;
            const int row = w * 32 + lane;
            uint4* xh = (uint4*)(smem + OFF_XHI + row * XPITCH);
            xh[0] = make_uint4(ph[0], ph[1], ph[2], ph[3]);
            xh[1] = make_uint4(ph[4], ph[5], ph[6], ph[7]);
        }
        __syncwarp();   // warp-private region: warp barrier suffices

        // ---- two sequential 16-row mma chunks, reusing accumulators ----
        #pragma unroll
        for (int half16 = 0; half16 < 2; half16++) {
            const uint32_t a_off = a_off0 + (uint32_t)(half16 * 16 * XPITCH);

            // layer 1: X(16x16) @ W1(16x64), weights resident
            float c1[32];
            #pragma unroll
            for (int i = 0; i < 32; i++) c1[i] = 0.0f;
            {
                uint32_t a1h[4];
                ldm4(sb + OFF_XHI + a_off, a1h[0], a1h[1], a1h[2], a1h[3]);
                #pragma unroll
                for (int jp = 0; jp < 8; jp += 2) {
                    mma16816(c1 + 4 * jp,     a1h, w1f[2 * jp + 0], w1f[2 * jp + 1]);
                    mma16816(c1 + 4 * jp + 4, a1h, w1f[2 * jp + 2], w1f[2 * jp + 3]);
                }
            }

            // layer 2, fused epilogue-1, weights resident
            float c2acc[32];
            #pragma unroll
            for (int i = 0; i < 32; i++) c2acc[i] = 0.0f;

            #pragma unroll
            for (int q = 0; q < 4; q++) {
                uint32_t a2h[4];
                #pragma unroll
                for (int jj = 0; jj < 2; jj++) {            // n-tiles j = 2q+jj
                    const int cjj = 8 * q + 4 * jj;
                    const float2 bia = *(const float2*)(smem + OFF_B1 + (8 * (2 * q + jj) + cb) * 4);
                    float v0 = silu(c1[cjj + 0] + bia.x);
                    float v1 = silu(c1[cjj + 1] + bia.y);
                    float v2 = silu(c1[cjj + 2] + bia.x);
                    float v3 = silu(c1[cjj + 3] + bia.y);
                    a2h[2 * jj + 0] = pack_hf2(v0, v1);
                    a2h[2 * jj + 1] = pack_hf2(v2, v3);
                }
                #pragma unroll
                for (int jp = 0; jp < 8; jp += 2) {
                    mma16816(c2acc + 4 * jp,     a2h, w2f[q * 16 + 2 * jp + 0], w2f[q * 16 + 2 * jp + 1]);
                    mma16816(c2acc + 4 * jp + 4, a2h, w2f[q * 16 + 2 * jp + 2], w2f[q * 16 + 2 * jp + 3]);
                }
            }

            // epilogue 2: bias + silu + layer3 + quad reduce + scatter
            float o0a = 0.f, o1a = 0.f, o0b = 0.f, o1b = 0.f;
            #pragma unroll
            for (int j = 0; j < 8; j++) {
                const int c0 = 8 * j + cb;
                const float2 bia = *(const float2*)(smem + OFF_B2 + c0 * 4);
                const float2 w3a = *(const float2*)(smem + OFF_W3 + c0 * 8);
                const float2 w3b = *(const float2*)(smem + OFF_W3 + (c0 + 1) * 8);
                float v0 = silu(c2acc[4 * j + 0] + bia.x);
                float v1 = silu(c2acc[4 * j + 1] + bia.y);
                float v2 = silu(c2acc[4 * j + 2] + bia.x);
                float v3 = silu(c2acc[4 * j + 3] + bia.y);
                o0a = fmaf(v0, w3a.x, fmaf(v1, w3b.x, o0a));
                o1a = fmaf(v0, w3a.y, fmaf(v1, w3b.y, o1a));
                o0b = fmaf(v2, w3a.x, fmaf(v3, w3b.x, o0b));
                o1b = fmaf(v2, w3a.y, fmaf(v3, w3b.y, o1b));
            }
            #pragma unroll
            for (int m = 1; m <= 2; m <<= 1) {
                o0a += __shfl_xor_sync(0xffffffffu, o0a, m);
                o1a += __shfl_xor_sync(0xffffffffu, o1a, m);
                o0b += __shfl_xor_sync(0xffffffffu, o0b, m);
                o1b += __shfl_xor_sync(0xffffffffu, o1b, m);
            }
            if ((lane & 3) == 0) {
                const int g = lane >> 2;
                #pragma unroll
                for (int hh = 0; hh < 2; hh++) {
                    const long long item = chunk * 32 + half16 * 16 + g + 8 * hh;
                    if (item < items) {
                        const int e = (int)(item >> 2);
                        const int s = (int)(item & 3);
                        int i_node;
                        if (is64) i_node = (int)((const long long*)edge)[e];
                        else      i_node = edge[e];
                        float* o = out + ((long long)i_node * S_SLOTS + s) * 2;
                        atomicAdd(o + 0, (hh ? o0b : o0a) + bb0);
                        atomicAdd(o + 1, (hh ? o1b : o1a) + bb1);
                    }
                }
            }
        }
        __syncwarp();   // ldmatrix reads done before next iteration overwrites
    }
}

extern "C" void kernel_launch(void* const* d_in, const int* in_sizes, int n_in,
                              void* d_out, int out_size) {
    const float* x     = (const float*)d_in[0];
    const float* theta = (const float*)d_in[1];
    const float* H     = (const float*)d_in[2];
    const int*   edge  = (const int*)d_in[3];
    const float* W1    = (const float*)d_in[4];
    const float* b1    = (const float*)d_in[5];
    const float* W2    = (const float*)d_in[6];
    const float* b2    = (const float*)d_in[7];
    const float* W3    = (const float*)d_in[8];
    const float* b3    = (const float*)d_in[9];

    const int nE = in_sizes[3] / 2;
    int nN = in_sizes[1];                  // theta has N elements
    if (nN > MAX_NODES) nN = MAX_NODES;

    const int init_n = (out_size > nN) ? out_size : nN;
    init_kernel<<<(init_n + 255) / 256, 256>>>((float*)d_out, out_size,
                                               edge, in_sizes[3], x, theta, nN);

    const long long items = (long long)nE * S_SLOTS;
    const int nchunks = (int)((items + 31) / 32);
    int grid = 2 * 148;                    // 2 persistent CTAs per SM
    gnn_mma_kernel<<<grid, NTHREADS>>>(H, edge,
                                       W1, b1, W2, b2, W3, b3,
                                       (float*)d_out, nE, nchunks);
}

// round 16
// speedup vs baseline: 1.3910x; 1.3910x over previous
#include <cuda_runtime.h>
#include <cuda_fp16.h>
#include <cstdint>

// FrameAlignedGNNLayer3D via mma.sync (sm_100-safe HMMA path).
// R16: base = R14 (best: 197us, 256thr/16 warps/SM, weights via in-loop
// ldmatrix — R15 proved register-residency kills occupancy and regresses).
// Epilogue overhaul per issue-slot audit (scalar epilogues ~700 of ~900
// slots/chunk):
//  (1) silu computed in half2 (tanh.approx.f16x2): ~half the instructions,
//      output doubles as the packed fp16 A-fragment.
//  (2) biases register-resident as per-lane half2 -> no epilogue LDS.
//  (3) layer-3 (64->2) as 4 mma using the L2-Cfrag==L3-Afrag chaining;
//      replaces 64 FFMA + 24 LDS + 8 SHFL per 16-row chunk.

#define S_SLOTS 4
#define NTHREADS 256
#define NWARPS 8
#define MAX_NODES (1 << 20)

// ---- smem layout (static, ~26KB) ----
#define XPITCH 48      // 16 fp16 (32B) + 16B pad -> conflict-free ldmatrix
#define WPITCH1 48
#define WPITCH2 144    // 64 fp16 (128B) + 16B pad
#define W3PITCH 144
#define OFF_XHI  0                              // 256 rows x 48B (warp-private 32-row regions)
#define OFF_W1H  (OFF_XHI + 256 * XPITCH)       // 12288
#define OFF_W2H  (OFF_W1H + 64 * WPITCH1)       // 15360
#define OFF_W3T  (OFF_W2H + 64 * WPITCH2)       // 24576: 8 rows x 64 fp16 (B-tile, rows 2..7 zero)
#define SMEM_BYTES (OFF_W3T + 8 * W3PITCH + 16)

__device__ int g_edge_is_i64;
__device__ float4 g_node_rec[MAX_NODES];   // {x0, x1, x2, theta}

__global__ void init_kernel(float* __restrict__ out, int n,
                            const int* __restrict__ edge32, int n32,
                            const float* __restrict__ x,
                            const float* __restrict__ theta, int nN) {
    int idx = blockIdx.x * blockDim.x + threadIdx.x;
    if (idx < n) out[idx] = 0.0f;
    if (idx < nN) {
        g_node_rec[idx] = make_float4(x[3 * idx + 0], x[3 * idx + 1],
                                      x[3 * idx + 2], theta[idx]);
    }
    if (idx == 0) {
        int any_nonzero = 0;
        for (int s = 0; s < 16; s++) {
            long long pos = 1 + (long long)s * ((n32 - 2) / 16);
            pos |= 1;
            if (pos < n32) any_nonzero |= (edge32[pos] != 0);
        }
        g_edge_is_i64 = any_nonzero ? 0 : 1;
    }
}

__device__ __forceinline__ uint32_t smem_u32(const void* p) {
    uint32_t a;
    asm("{ .reg .u64 t; cvta.to.shared.u64 t, %1; cvt.u32.u64 %0, t; }" : "=r"(a) : "l"(p));
    return a;
}

__device__ __forceinline__ void ldm4(uint32_t addr, uint32_t& r0, uint32_t& r1,
                                     uint32_t& r2, uint32_t& r3) {
    asm volatile("ldmatrix.sync.aligned.m8n8.x4.shared.b16 {%0,%1,%2,%3}, [%4];"
                 : "=r"(r0), "=r"(r1), "=r"(r2), "=r"(r3) : "r"(addr));
}

__device__ __forceinline__ void mma16816(float* c, const uint32_t* a,
                                         uint32_t b0, uint32_t b1) {
    asm volatile(
        "mma.sync.aligned.m16n8k16.row.col.f32.f16.f16.f32 "
        "{%0,%1,%2,%3}, {%4,%5,%6,%7}, {%8,%9}, {%0,%1,%2,%3};"
        : "+f"(c[0]), "+f"(c[1]), "+f"(c[2]), "+f"(c[3])
        : "r"(a[0]), "r"(a[1]), "r"(a[2]), "r"(a[3]), "r"(b0), "r"(b1));
}

__device__ __forceinline__ uint32_t pack_hf2(float v0, float v1) {
    __half2 p = __floats2half2_rn(v0, v1);   // .x = v0 (low half)
    return *reinterpret_cast<uint32_t*>(&p);
}

// silu on a packed half2 after adding a packed half2 bias:
// x = v + bias; h = 0.5x; t = tanh(h); r = h*t + h   (all f16x2)
__device__ __forceinline__ uint32_t silu2_bias(uint32_t vb, uint32_t biasb) {
    __half2 v = *reinterpret_cast<__half2*>(&vb);
    __half2 bia = *reinterpret_cast<__half2*>(&biasb);
    __half2 x = __hadd2(v, bia);
    __half2 h = __hmul2(x, __float2half2_rn(0.5f));
    uint32_t hb = *reinterpret_cast<uint32_t*>(&h);
    uint32_t tb;
    asm("tanh.approx.f16x2 %0, %1;" : "=r"(tb) : "r"(hb));
    __half2 tt = *reinterpret_cast<__half2*>(&tb);
    __half2 r = __hfma2(h, tt, h);
    return *reinterpret_cast<uint32_t*>(&r);
}

__global__ __launch_bounds__(NTHREADS, 2)
void gnn_mma_kernel(
    const float* __restrict__ H, const int* __restrict__ edge,
    const float* __restrict__ W1, const float* __restrict__ b1,
    const float* __restrict__ W2, const float* __restrict__ b2,
    const float* __restrict__ W3, const float* __restrict__ b3,
    float* __restrict__ out, int nE, int nchunks)
{
    __shared__ __align__(16) char smem[SMEM_BYTES];
    const uint32_t sb = smem_u32(smem);

    const int t    = threadIdx.x;
    const int lane = t & 31;
    const int w    = t >> 5;           // warp id 0..7
    const int is64 = g_edge_is_i64;
    const long long items = (long long)nE * S_SLOTS;

    // ================= stage weights ONCE per block (single fp16) ============
    for (int idx = t; idx < 64 * 10; idx += NTHREADS) {
        int kk = idx / 64, n = idx % 64;
        *(__half*)(smem + OFF_W1H + n * WPITCH1 + kk * 2) = __float2half_rn(W1[kk * 64 + n]);
    }
    if (t < 64) {  // zero pad kk 10..15 of W1
        for (int kk = 10; kk < 16; kk++)
            *(__half*)(smem + OFF_W1H + t * WPITCH1 + kk * 2) = __float2half_rn(0.f);
    }
    for (int idx = t; idx < 64 * 64; idx += NTHREADS) {
        int k = idx >> 6, n = idx & 63;
        *(__half*)(smem + OFF_W2H + n * WPITCH2 + k * 2) = __float2half_rn(W2[k * 64 + n]);
    }
    // W3 B-tile: rows n=0..7 (only 0,1 real), cols k=0..63
    for (int idx = t; idx < 8 * 64; idx += NTHREADS) {
        int n = idx >> 6, k = idx & 63;
        float v = (n < 2) ? W3[k * 2 + n] : 0.0f;
        *(__half*)(smem + OFF_W3T + n * W3PITCH + k * 2) = __float2half_rn(v);
    }
    __syncthreads();   // ONLY block barrier.

    // ================= ldmatrix address precompute =================
    const int sel = lane >> 3;
    const int r8  = lane & 7;
    const uint32_t a_off0 = (uint32_t)((w * 32 + r8 + (sel & 1) * 8) * XPITCH + (sel >> 1) * 16);
    const uint32_t w1_off = (uint32_t)(((sel >> 1) * 8 + r8) * WPITCH1 + (sel & 1) * 16);
    const uint32_t w2_off = (uint32_t)(((sel >> 1) * 8 + r8) * WPITCH2 + (sel & 1) * 16);
    const int cb = 2 * (lane & 3);

    // ---- W3 B-fragments (8 regs): k-tiles 0..3 of the single n-tile ----
    uint32_t w3f[8];
    {
        const uint32_t w3_off = (uint32_t)(r8 * W3PITCH + sel * 16);
        ldm4(sb + OFF_W3T + w3_off,      w3f[0], w3f[1], w3f[2], w3f[3]);   // k 0..31
        ldm4(sb + OFF_W3T + w3_off + 64, w3f[4], w3f[5], w3f[6], w3f[7]);   // k 32..63
    }

    // ---- biases register-resident as per-lane half2 ----
    uint32_t bias1h[8], bias2h[8];
    #pragma unroll
    for (int j = 0; j < 8; j++) {
        bias1h[j] = pack_hf2(b1[8 * j + cb], b1[8 * j + cb + 1]);
        bias2h[j] = pack_hf2(b2[8 * j + cb], b2[8 * j + cb + 1]);
    }
    const float bb0 = b3[0];
    const float bb1 = b3[1];

    const int gw = blockIdx.x * NWARPS + w;     // global warp id
    const int TW = gridDim.x * NWARPS;          // total warps

    // ================= warp-autonomous chunk loop (32 rows/chunk) ============
    for (long long chunk = gw; chunk < nchunks; chunk += TW) {

        // ---- features: every lane computes one row into warp-private smem ----
        {
            const long long item = chunk * 32 + lane;
            float f[10] = {0, 0, 0, 0, 0, 0, 0, 0, 0, 0};
            if (item < items) {
                const int e = (int)(item >> 2);
                const int s = (int)(item & 3);
                int i_node, j_node;
                if (is64) {
                    const long long* e64 = (const long long*)edge;
                    i_node = (int)e64[e]; j_node = (int)e64[(long long)nE + e];
                } else {
                    i_node = edge[e]; j_node = edge[nE + e];
                }
                const float4 ri = g_node_rec[i_node];
                const float4 rj = g_node_rec[j_node];
                const float dx0 = rj.x - ri.x;
                const float dx1 = rj.y - ri.y;
                const float dx2 = rj.z - ri.z;
                const float rxy2 = dx0 * dx0 + dx1 * dx1;
                float s2, c2; sincosf(2.0f * (rj.w - ri.w), &s2, &c2);
                float sp, cp; sincosf(atan2f(dx1, dx0) - ri.w, &sp, &cp);
                const float sgn = (dx2 > 0.0f) ? 1.0f : ((dx2 < 0.0f) ? -1.0f : 0.0f);
                const float2 hv = *(const float2*)(H + ((long long)j_node * S_SLOTS + s) * 2);
                f[0] = c2 * hv.x - s2 * hv.y;
                f[1] = s2 * hv.x + c2 * hv.y;
                f[2] = sqrtf(rxy2 + dx2 * dx2);
                f[3] = sqrtf(rxy2);
                f[4] = dx2;
                f[5] = sp;  f[6] = cp;  f[7] = s2;  f[8] = c2;  f[9] = sgn * s2;
            }
            uint32_t ph[8];
            #pragma unroll
            for (int c = 0; c < 10; c += 2)
                ph[c >> 1] = pack_hf2(f[c], f[c + 1]);
            ph[5] = 0u; ph[6] = 0u; ph[7] = 0u;
            const int row = w * 32 + lane;
            uint4* xh = (uint4*)(smem + OFF_XHI + row * XPITCH);
            xh[0] = make_uint4(ph[0], ph[1], ph[2], ph[3]);
            xh[1] = make_uint4(ph[4], ph[5], ph[6], ph[7]);
        }
        __syncwarp();   // warp-private region: warp barrier suffices

        // ---- two sequential 16-row mma chunks, reusing accumulators ----
        #pragma unroll
        for (int half16 = 0; half16 < 2; half16++) {
            const uint32_t a_off = a_off0 + (uint32_t)(half16 * 16 * XPITCH);

            // layer 1: X(16x16) @ W1(16x64)
            float c1[32];
            #pragma unroll
            for (int i = 0; i < 32; i++) c1[i] = 0.0f;
            {
                uint32_t a1h[4];
                ldm4(sb + OFF_XHI + a_off, a1h[0], a1h[1], a1h[2], a1h[3]);
                #pragma unroll
                for (int jp = 0; jp < 8; jp += 2) {
                    uint32_t wh0, wh1, wh2, wh3;
                    ldm4(sb + OFF_W1H + jp * 8 * WPITCH1 + w1_off, wh0, wh1, wh2, wh3);
                    mma16816(c1 + 4 * jp,     a1h, wh0, wh1);
                    mma16816(c1 + 4 * jp + 4, a1h, wh2, wh3);
                }
            }

            // layer 2 with fused half2-silu epilogue-1
            float c2acc[32];
            #pragma unroll
            for (int i = 0; i < 32; i++) c2acc[i] = 0.0f;

            #pragma unroll
            for (int q = 0; q < 4; q++) {
                uint32_t a2h[4];
                #pragma unroll
                for (int jj = 0; jj < 2; jj++) {            // n-tiles j = 2q+jj
                    const int j = 2 * q + jj;
                    const int cjj = 8 * q + 4 * jj;
                    a2h[2 * jj + 0] = silu2_bias(pack_hf2(c1[cjj + 0], c1[cjj + 1]), bias1h[j]);
                    a2h[2 * jj + 1] = silu2_bias(pack_hf2(c1[cjj + 2], c1[cjj + 3]), bias1h[j]);
                }
                #pragma unroll
                for (int jp = 0; jp < 8; jp += 2) {
                    uint32_t wh0, wh1, wh2, wh3;
                    ldm4(sb + OFF_W2H + jp * 8 * WPITCH2 + q * 32 + w2_off, wh0, wh1, wh2, wh3);
                    mma16816(c2acc + 4 * jp,     a2h, wh0, wh1);
                    mma16816(c2acc + 4 * jp + 4, a2h, wh2, wh3);
                }
            }

            // epilogue 2: half2 silu + layer-3 AS MMA (C-frag==A-frag chaining)
            float o[4];
            o[0] = 0.f; o[1] = 0.f; o[2] = 0.f; o[3] = 0.f;
            #pragma unroll
            for (int q = 0; q < 4; q++) {
                uint32_t a3h[4];
                #pragma unroll
                for (int jj = 0; jj < 2; jj++) {
                    const int j = 2 * q + jj;
                    const int cjj = 8 * q + 4 * jj;
                    a3h[2 * jj + 0] = silu2_bias(pack_hf2(c2acc[cjj + 0], c2acc[cjj + 1]), bias2h[j]);
                    a3h[2 * jj + 1] = silu2_bias(pack_hf2(c2acc[cjj + 2], c2acc[cjj + 3]), bias2h[j]);
                }
                mma16816(o, a3h, w3f[2 * q], w3f[2 * q + 1]);
            }
            // lanes t=0 (cb==0): o[0,1] = (o0,o1) row g ; o[2,3] = row g+8
            if ((lane & 3) == 0) {
                const int g = lane >> 2;
                #pragma unroll
                for (int hh = 0; hh < 2; hh++) {
                    const long long item = chunk * 32 + half16 * 16 + g + 8 * hh;
                    if (item < items) {
                        const int e = (int)(item >> 2);
                        const int s = (int)(item & 3);
                        int i_node;
                        if (is64) i_node = (int)((const long long*)edge)[e];
                        else      i_node = edge[e];
                        float* op = out + ((long long)i_node * S_SLOTS + s) * 2;
                        atomicAdd(op + 0, o[2 * hh + 0] + bb0);
                        atomicAdd(op + 1, o[2 * hh + 1] + bb1);
                    }
                }
            }
        }
        __syncwarp();   // ldmatrix reads done before next iteration overwrites
    }
}

extern "C" void kernel_launch(void* const* d_in, const int* in_sizes, int n_in,
                              void* d_out, int out_size) {
    const float* x     = (const float*)d_in[0];
    const float* theta = (const float*)d_in[1];
    const float* H     = (const float*)d_in[2];
    const int*   edge  = (const int*)d_in[3];
    const float* W1    = (const float*)d_in[4];
    const float* b1    = (const float*)d_in[5];
    const float* W2    = (const float*)d_in[6];
    const float* b2    = (const float*)d_in[7];
    const float* W3    = (const float*)d_in[8];
    const float* b3    = (const float*)d_in[9];

    const int nE = in_sizes[3] / 2;
    int nN = in_sizes[1];                  // theta has N elements
    if (nN > MAX_NODES) nN = MAX_NODES;

    const int init_n = (out_size > nN) ? out_size : nN;
    init_kernel<<<(init_n + 255) / 256, 256>>>((float*)d_out, out_size,
                                               edge, in_sizes[3], x, theta, nN);

    const long long items = (long long)nE * S_SLOTS;
    const int nchunks = (int)((items + 31) / 32);
    int grid = 2 * 148;                    // 2 persistent CTAs per SM
    gnn_mma_kernel<<<grid, NTHREADS>>>(H, edge,
                                       W1, b1, W2, b2, W3, b3,
                                       (float*)d_out, nE, nchunks);
}

// round 17
// speedup vs baseline: 1.5020x; 1.0798x over previous
#include <cuda_runtime.h>
#include <cuda_fp16.h>
#include <cstdint>

// FrameAlignedGNNLayer3D via mma.sync (sm_100-safe HMMA path).
// R17: per-node trig precompute. R16 profile: fma+alu 52% combined; feature
// phase runs 2x sincosf + atan2f per item (~140 warp-issues/chunk). All trig
// depends only on per-node theta -> init kernel stores {sin,cos,sin2,cos2}
// per node; per-edge trig becomes FMA angle-sum identities + one rsqrt.
// (atan2(0,0)=0 degenerate edges guarded with selects.)
// Keeps R16: half2 epilogues, register biases, layer-3 as mma, 16 warps/SM.

#define S_SLOTS 4
#define NTHREADS 256
#define NWARPS 8
#define MAX_NODES (1 << 20)

// ---- smem layout (static, ~26KB) ----
#define XPITCH 48      // 16 fp16 (32B) + 16B pad -> conflict-free ldmatrix
#define WPITCH1 48
#define WPITCH2 144    // 64 fp16 (128B) + 16B pad
#define W3PITCH 144
#define OFF_XHI  0                              // 256 rows x 48B (warp-private 32-row regions)
#define OFF_W1H  (OFF_XHI + 256 * XPITCH)       // 12288
#define OFF_W2H  (OFF_W1H + 64 * WPITCH1)       // 15360
#define OFF_W3T  (OFF_W2H + 64 * WPITCH2)       // 24576: 8 rows x 64 fp16 (B-tile, rows 2..7 zero)
#define SMEM_BYTES (OFF_W3T + 8 * W3PITCH + 16)

__device__ int g_edge_is_i64;
__device__ float4 g_node_pos[MAX_NODES];    // {x0, x1, x2, --}
__device__ float4 g_node_trig[MAX_NODES];   // {sin t, cos t, sin 2t, cos 2t}

__global__ void init_kernel(float* __restrict__ out, int n,
                            const int* __restrict__ edge32, int n32,
                            const float* __restrict__ x,
                            const float* __restrict__ theta, int nN) {
    int idx = blockIdx.x * blockDim.x + threadIdx.x;
    if (idx < n) out[idx] = 0.0f;
    if (idx < nN) {
        const float th = theta[idx];
        float s1, c1v, s2, c2v;
        sincosf(th, &s1, &c1v);
        sincosf(2.0f * th, &s2, &c2v);
        g_node_pos[idx]  = make_float4(x[3 * idx + 0], x[3 * idx + 1],
                                       x[3 * idx + 2], 0.0f);
        g_node_trig[idx] = make_float4(s1, c1v, s2, c2v);
    }
    if (idx == 0) {
        int any_nonzero = 0;
        for (int s = 0; s < 16; s++) {
            long long pos = 1 + (long long)s * ((n32 - 2) / 16);
            pos |= 1;
            if (pos < n32) any_nonzero |= (edge32[pos] != 0);
        }
        g_edge_is_i64 = any_nonzero ? 0 : 1;
    }
}

__device__ __forceinline__ uint32_t smem_u32(const void* p) {
    uint32_t a;
    asm("{ .reg .u64 t; cvta.to.shared.u64 t, %1; cvt.u32.u64 %0, t; }" : "=r"(a) : "l"(p));
    return a;
}

__device__ __forceinline__ void ldm4(uint32_t addr, uint32_t& r0, uint32_t& r1,
                                     uint32_t& r2, uint32_t& r3) {
    asm volatile("ldmatrix.sync.aligned.m8n8.x4.shared.b16 {%0,%1,%2,%3}, [%4];"
                 : "=r"(r0), "=r"(r1), "=r"(r2), "=r"(r3) : "r"(addr));
}

__device__ __forceinline__ void mma16816(float* c, const uint32_t* a,
                                         uint32_t b0, uint32_t b1) {
    asm volatile(
        "mma.sync.aligned.m16n8k16.row.col.f32.f16.f16.f32 "
        "{%0,%1,%2,%3}, {%4,%5,%6,%7}, {%8,%9}, {%0,%1,%2,%3};"
        : "+f"(c[0]), "+f"(c[1]), "+f"(c[2]), "+f"(c[3])
        : "r"(a[0]), "r"(a[1]), "r"(a[2]), "r"(a[3]), "r"(b0), "r"(b1));
}

__device__ __forceinline__ uint32_t pack_hf2(float v0, float v1) {
    __half2 p = __floats2half2_rn(v0, v1);   // .x = v0 (low half)
    return *reinterpret_cast<uint32_t*>(&p);
}

// silu on a packed half2 after adding a packed half2 bias.
__device__ __forceinline__ uint32_t silu2_bias(uint32_t vb, uint32_t biasb) {
    __half2 v = *reinterpret_cast<__half2*>(&vb);
    __half2 bia = *reinterpret_cast<__half2*>(&biasb);
    __half2 xx = __hadd2(v, bia);
    __half2 h = __hmul2(xx, __float2half2_rn(0.5f));
    uint32_t hb = *reinterpret_cast<uint32_t*>(&h);
    uint32_t tb;
    asm("tanh.approx.f16x2 %0, %1;" : "=r"(tb) : "r"(hb));
    __half2 tt = *reinterpret_cast<__half2*>(&tb);
    __half2 r = __hfma2(h, tt, h);
    return *reinterpret_cast<uint32_t*>(&r);
}

__global__ __launch_bounds__(NTHREADS, 2)
void gnn_mma_kernel(
    const float* __restrict__ H, const int* __restrict__ edge,
    const float* __restrict__ W1, const float* __restrict__ b1,
    const float* __restrict__ W2, const float* __restrict__ b2,
    const float* __restrict__ W3, const float* __restrict__ b3,
    float* __restrict__ out, int nE, int nchunks)
{
    __shared__ __align__(16) char smem[SMEM_BYTES];
    const uint32_t sb = smem_u32(smem);

    const int t    = threadIdx.x;
    const int lane = t & 31;
    const int w    = t >> 5;           // warp id 0..7
    const int is64 = g_edge_is_i64;
    const long long items = (long long)nE * S_SLOTS;

    // ================= stage weights ONCE per block (single fp16) ============
    for (int idx = t; idx < 64 * 10; idx += NTHREADS) {
        int kk = idx / 64, n = idx % 64;
        *(__half*)(smem + OFF_W1H + n * WPITCH1 + kk * 2) = __float2half_rn(W1[kk * 64 + n]);
    }
    if (t < 64) {  // zero pad kk 10..15 of W1
        for (int kk = 10; kk < 16; kk++)
            *(__half*)(smem + OFF_W1H + t * WPITCH1 + kk * 2) = __float2half_rn(0.f);
    }
    for (int idx = t; idx < 64 * 64; idx += NTHREADS) {
        int k = idx >> 6, n = idx & 63;
        *(__half*)(smem + OFF_W2H + n * WPITCH2 + k * 2) = __float2half_rn(W2[k * 64 + n]);
    }
    // W3 B-tile: rows n=0..7 (only 0,1 real), cols k=0..63
    for (int idx = t; idx < 8 * 64; idx += NTHREADS) {
        int n = idx >> 6, k = idx & 63;
        float v = (n < 2) ? W3[k * 2 + n] : 0.0f;
        *(__half*)(smem + OFF_W3T + n * W3PITCH + k * 2) = __float2half_rn(v);
    }
    __syncthreads();   // ONLY block barrier.

    // ================= ldmatrix address precompute =================
    const int sel = lane >> 3;
    const int r8  = lane & 7;
    const uint32_t a_off0 = (uint32_t)((w * 32 + r8 + (sel & 1) * 8) * XPITCH + (sel >> 1) * 16);
    const uint32_t w1_off = (uint32_t)(((sel >> 1) * 8 + r8) * WPITCH1 + (sel & 1) * 16);
    const uint32_t w2_off = (uint32_t)(((sel >> 1) * 8 + r8) * WPITCH2 + (sel & 1) * 16);
    const int cb = 2 * (lane & 3);

    // ---- W3 B-fragments (8 regs): k-tiles 0..3 of the single n-tile ----
    uint32_t w3f[8];
    {
        const uint32_t w3_off = (uint32_t)(r8 * W3PITCH + sel * 16);
        ldm4(sb + OFF_W3T + w3_off,      w3f[0], w3f[1], w3f[2], w3f[3]);   // k 0..31
        ldm4(sb + OFF_W3T + w3_off + 64, w3f[4], w3f[5], w3f[6], w3f[7]);   // k 32..63
    }

    // ---- biases register-resident as per-lane half2 ----
    uint32_t bias1h[8], bias2h[8];
    #pragma unroll
    for (int j = 0; j < 8; j++) {
        bias1h[j] = pack_hf2(b1[8 * j + cb], b1[8 * j + cb + 1]);
        bias2h[j] = pack_hf2(b2[8 * j + cb], b2[8 * j + cb + 1]);
    }
    const float bb0 = b3[0];
    const float bb1 = b3[1];

    const int gw = blockIdx.x * NWARPS + w;     // global warp id
    const int TW = gridDim.x * NWARPS;          // total warps

    // ================= warp-autonomous chunk loop (32 rows/chunk) ============
    for (long long chunk = gw; chunk < nchunks; chunk += TW) {

        // ---- features: algebraic trig via per-node precomputed sin/cos ----
        {
            const long long item = chunk * 32 + lane;
            float f[10] = {0, 0, 0, 0, 0, 0, 0, 0, 0, 0};
            if (item < items) {
                const int e = (int)(item >> 2);
                const int s = (int)(item & 3);
                int i_node, j_node;
                if (is64) {
                    const long long* e64 = (const long long*)edge;
                    i_node = (int)e64[e]; j_node = (int)e64[(long long)nE + e];
                } else {
                    i_node = edge[e]; j_node = edge[nE + e];
                }
                const float4 pi4 = g_node_pos[i_node];
                const float4 pj4 = g_node_pos[j_node];
                const float4 ti4 = g_node_trig[i_node];   // {sin, cos, sin2, cos2}
                const float4 tj4 = g_node_trig[j_node];

                const float dx0 = pj4.x - pi4.x;
                const float dx1 = pj4.y - pi4.y;
                const float dx2 = pj4.z - pi4.z;
                const float rxy2 = dx0 * dx0 + dx1 * dx1;
                const bool ok = (rxy2 > 0.0f);
                const float rinv = rsqrtf(rxy2);          // inf if rxy2==0 (guarded)
                const float rxy  = ok ? rxy2 * rinv : 0.0f;
                const float cphi = ok ? dx0 * rinv : 1.0f;   // atan2(0,0)=0 -> phi=0
                const float sphi = ok ? dx1 * rinv : 0.0f;
                // sin/cos(phi - theta_i)
                const float sp = sphi * ti4.y - cphi * ti4.x;
                const float cp = cphi * ti4.y + sphi * ti4.x;
                // sin/cos(2(theta_j - theta_i))
                const float s2 = tj4.z * ti4.w - tj4.w * ti4.z;
                const float c2 = tj4.w * ti4.w + tj4.z * ti4.z;
                const float sgn = (dx2 > 0.0f) ? 1.0f : ((dx2 < 0.0f) ? -1.0f : 0.0f);
                const float2 hv = *(const float2*)(H + ((long long)j_node * S_SLOTS + s) * 2);
                f[0] = c2 * hv.x - s2 * hv.y;
                f[1] = s2 * hv.x + c2 * hv.y;
                f[2] = sqrtf(rxy2 + dx2 * dx2);
                f[3] = rxy;
                f[4] = dx2;
                f[5] = sp;  f[6] = cp;  f[7] = s2;  f[8] = c2;  f[9] = sgn * s2;
            }
            uint32_t ph[8];
            #pragma unroll
            for (int c = 0; c < 10; c += 2)
                ph[c >> 1] = pack_hf2(f[c], f[c + 1]);
            ph[5] = 0u; ph[6] = 0u; ph[7] = 0u;
            const int row = w * 32 + lane;
            uint4* xh = (uint4*)(smem + OFF_XHI + row * XPITCH);
            xh[0] = make_uint4(ph[0], ph[1], ph[2], ph[3]);
            xh[1] = make_uint4(ph[4], ph[5], ph[6], ph[7]);
        }
        __syncwarp();   // warp-private region: warp barrier suffices

        // ---- two sequential 16-row mma chunks, reusing accumulators ----
        #pragma unroll
        for (int half16 = 0; half16 < 2; half16++) {
            const uint32_t a_off = a_off0 + (uint32_t)(half16 * 16 * XPITCH);

            // layer 1: X(16x16) @ W1(16x64)
            float c1[32];
            #pragma unroll
            for (int i = 0; i < 32; i++) c1[i] = 0.0f;
            {
                uint32_t a1h[4];
                ldm4(sb + OFF_XHI + a_off, a1h[0], a1h[1], a1h[2], a1h[3]);
                #pragma unroll
                for (int jp = 0; jp < 8; jp += 2) {
                    uint32_t wh0, wh1, wh2, wh3;
                    ldm4(sb + OFF_W1H + jp * 8 * WPITCH1 + w1_off, wh0, wh1, wh2, wh3);
                    mma16816(c1 + 4 * jp,     a1h, wh0, wh1);
                    mma16816(c1 + 4 * jp + 4, a1h, wh2, wh3);
                }
            }

            // layer 2 with fused half2-silu epilogue-1
            float c2acc[32];
            #pragma unroll
            for (int i = 0; i < 32; i++) c2acc[i] = 0.0f;

            #pragma unroll
            for (int q = 0; q < 4; q++) {
                uint32_t a2h[4];
                #pragma unroll
                for (int jj = 0; jj < 2; jj++) {            // n-tiles j = 2q+jj
                    const int j = 2 * q + jj;
                    const int cjj = 8 * q + 4 * jj;
                    a2h[2 * jj + 0] = silu2_bias(pack_hf2(c1[cjj + 0], c1[cjj + 1]), bias1h[j]);
                    a2h[2 * jj + 1] = silu2_bias(pack_hf2(c1[cjj + 2], c1[cjj + 3]), bias1h[j]);
                }
                #pragma unroll
                for (int jp = 0; jp < 8; jp += 2) {
                    uint32_t wh0, wh1, wh2, wh3;
                    ldm4(sb + OFF_W2H + jp * 8 * WPITCH2 + q * 32 + w2_off, wh0, wh1, wh2, wh3);
                    mma16816(c2acc + 4 * jp,     a2h, wh0, wh1);
                    mma16816(c2acc + 4 * jp + 4, a2h, wh2, wh3);
                }
            }

            // epilogue 2: half2 silu + layer-3 AS MMA (C-frag==A-frag chaining)
            float o[4];
            o[0] = 0.f; o[1] = 0.f; o[2] = 0.f; o[3] = 0.f;
            #pragma unroll
            for (int q = 0; q < 4; q++) {
                uint32_t a3h[4];
                #pragma unroll
                for (int jj = 0; jj < 2; jj++) {
                    const int j = 2 * q + jj;
                    const int cjj = 8 * q + 4 * jj;
                    a3h[2 * jj + 0] = silu2_bias(pack_hf2(c2acc[cjj + 0], c2acc[cjj + 1]), bias2h[j]);
                    a3h[2 * jj + 1] = silu2_bias(pack_hf2(c2acc[cjj + 2], c2acc[cjj + 3]), bias2h[j]);
                }
                mma16816(o, a3h, w3f[2 * q], w3f[2 * q + 1]);
            }
            // lanes with cb==0: o[0,1] = (o0,o1) row g ; o[2,3] = row g+8
            if ((lane & 3) == 0) {
                const int g = lane >> 2;
                #pragma unroll
                for (int hh = 0; hh < 2; hh++) {
                    const long long item = chunk * 32 + half16 * 16 + g + 8 * hh;
                    if (item < items) {
                        const int e = (int)(item >> 2);
                        const int s = (int)(item & 3);
                        int i_node;
                        if (is64) i_node = (int)((const long long*)edge)[e];
                        else      i_node = edge[e];
                        float* op = out + ((long long)i_node * S_SLOTS + s) * 2;
                        atomicAdd(op + 0, o[2 * hh + 0] + bb0);
                        atomicAdd(op + 1, o[2 * hh + 1] + bb1);
                    }
                }
            }
        }
        __syncwarp();   // ldmatrix reads done before next iteration overwrites
    }
}

extern "C" void kernel_launch(void* const* d_in, const int* in_sizes, int n_in,
                              void* d_out, int out_size) {
    const float* x     = (const float*)d_in[0];
    const float* theta = (const float*)d_in[1];
    const float* H     = (const float*)d_in[2];
    const int*   edge  = (const int*)d_in[3];
    const float* W1    = (const float*)d_in[4];
    const float* b1    = (const float*)d_in[5];
    const float* W2    = (const float*)d_in[6];
    const float* b2    = (const float*)d_in[7];
    const float* W3    = (const float*)d_in[8];
    const float* b3    = (const float*)d_in[9];

    const int nE = in_sizes[3] / 2;
    int nN = in_sizes[1];                  // theta has N elements
    if (nN > MAX_NODES) nN = MAX_NODES;

    const int init_n = (out_size > nN) ? out_size : nN;
    init_kernel<<<(init_n + 255) / 256, 256>>>((float*)d_out, out_size,
                                               edge, in_sizes[3], x, theta, nN);

    const long long items = (long long)nE * S_SLOTS;
    const int nchunks = (int)((items + 31) / 32);
    int grid = 2 * 148;                    // 2 persistent CTAs per SM
    gnn_mma_kernel<<<grid, NTHREADS>>>(H, edge,
                                       W1, b1, W2, b2, W3, b3,
                                       (float*)d_out, nE, nchunks);
}